// round 4
// baseline (speedup 1.0000x reference)
#include <cuda_runtime.h>
#include <math.h>

#define FEAT 44
#define TED 84
#define HALF_TED 42
#define DIN 128
#define H0 64
#define H1 32
#define MAXB 4096
#define LN_SIGMA 3.2188758248682006f   /* ln(25) */
#define TWO_PI 6.28318530717958647692f

typedef unsigned long long u64;

// Scratch (no dynamic allocation allowed)
__device__ float g_emb[MAXB * TED];
__device__ float g_e0[MAXB * H0];
__device__ float g_invstd[MAXB];

__device__ __forceinline__ float swishf(float x) {
    return __fdividef(x, 1.0f + __expf(-x));
}

// ---- packed f32x2 helpers (Blackwell FFMA2: 2 fp32 FMAs per instruction) ----
__device__ __forceinline__ u64 ffma2(u64 a, u64 b, u64 c) {
    u64 d;
    asm("fma.rn.f32x2 %0, %1, %2, %3;" : "=l"(d) : "l"(a), "l"(b), "l"(c));
    return d;
}
__device__ __forceinline__ u64 pack2(float lo, float hi) {
    u64 r;
    asm("mov.b64 %0, {%1, %2};" : "=l"(r) : "f"(lo), "f"(hi));
    return r;
}
__device__ __forceinline__ void unpack2(u64 v, float& lo, float& hi) {
    asm("mov.b64 {%0, %1}, %2;" : "=f"(lo), "=f"(hi) : "l"(v));
}

// ---------------------------------------------------------------------------
// Kernel 1a: per-graph Fourier embedding + embed Linear(84->84)+swish, invstd
// ---------------------------------------------------------------------------
__global__ __launch_bounds__(128) void k_embed(
    const float* __restrict__ t, const float* __restrict__ W_f,
    const float* __restrict__ ew, const float* __restrict__ eb, int B)
{
    __shared__ float s_ewT[TED * TED];
    __shared__ float s_wf[HALF_TED];
    __shared__ float s_eb[TED];
    __shared__ float s_temb[TED];

    int tid = threadIdx.x;
    for (int idx = tid; idx < TED * TED; idx += blockDim.x) {
        int j = idx / TED, i = idx - j * TED;
        s_ewT[i * TED + j] = ew[idx];
    }
    if (tid < HALF_TED) s_wf[tid] = W_f[tid];
    if (tid < TED)      s_eb[tid] = eb[tid];
    __syncthreads();

    for (int g = blockIdx.x; g < B; g += gridDim.x) {
        float tg = t[g];
        if (tid < HALF_TED) {
            float xp = tg * s_wf[tid] * TWO_PI;
            float s, c;
            sincosf(xp, &s, &c);
            s_temb[tid] = s;
            s_temb[tid + HALF_TED] = c;
        }
        if (tid == blockDim.x - 1) {
            float v = (expf(2.0f * tg * LN_SIGMA) - 1.0f) * (0.5f / LN_SIGMA);
            g_invstd[g] = rsqrtf(v);
        }
        __syncthreads();
        if (tid < TED) {
            float acc = s_eb[tid];
            #pragma unroll 4
            for (int i = 0; i < TED; i++)
                acc = fmaf(s_temb[i], s_ewT[i * TED + tid], acc);
            g_emb[g * TED + tid] = swishf(acc);
        }
        __syncthreads();
    }
}

// ---------------------------------------------------------------------------
// Kernel 1b: per-graph e0[g][64] = b0 + embed[g] @ w0[:, 44:128].T
// ---------------------------------------------------------------------------
__global__ __launch_bounds__(128) void k_e0(
    const float* __restrict__ w0, const float* __restrict__ b0, int B)
{
    __shared__ float s_w0t[TED * H0];
    __shared__ float s_b0[H0];

    int tid = threadIdx.x;
    for (int idx = tid; idx < TED * H0; idx += blockDim.x) {
        int i = idx / H0, j = idx - i * H0;
        s_w0t[idx] = w0[j * DIN + FEAT + i];
    }
    if (tid < H0) s_b0[tid] = b0[tid];
    __syncthreads();

    for (int g = blockIdx.x; g < B; g += gridDim.x) {
        if (tid < H0) {
            const float* er = g_emb + g * TED;
            float acc = s_b0[tid];
            #pragma unroll 4
            for (int i = 0; i < TED; i++)
                acc = fmaf(__ldg(&er[i]), s_w0t[i * H0 + tid], acc);
            g_e0[g * H0 + tid] = acc;
        }
    }
}

// ---------------------------------------------------------------------------
// Kernel 2: per-node MLP, packed f32x2 math throughout.
//  L0: 22 packed FMAs per output row (K=44 features; embed-half precomputed),
//      e0 folded into lo lane of the packed accumulator (no extra FADD chain).
//  L1: h broadcast into both lanes, 16 packed FMAs scatter into 32 accumulators.
//  L2: 2 packed FMAs per row into {o0,o1},{o2,o3}.
// ---------------------------------------------------------------------------
__global__ __launch_bounds__(256) void k_main(
    const float* __restrict__ node_attr, const int* __restrict__ ptr,
    const float* __restrict__ w0, const float* __restrict__ w1,
    const float* __restrict__ b1, const float* __restrict__ w2,
    const float* __restrict__ b2, float* __restrict__ out,
    int n, int B)
{
    __shared__ int s_ptr[MAXB + 1];
    __shared__ u64 s_w0p[H0 * 22];   // [j][k2] = {w0[j][2k2], w0[j][2k2+1]}, feature part
    __shared__ u64 s_w1p[H0 * 16];   // [k][q]  = {w1[2q][k], w1[2q+1][k]}
    __shared__ u64 s_w2p01[H1];      // [k] = {w2[0][k], w2[1][k]}
    __shared__ u64 s_w2p23[H1];      // [k] = {w2[2][k], w2[3][k]}

    int tid = threadIdx.x;
    for (int idx = tid; idx <= B; idx += 256) s_ptr[idx] = ptr[idx];
    for (int idx = tid; idx < H0 * 22; idx += 256) {
        int j = idx / 22, k2 = idx - j * 22;
        float2 v = *(const float2*)&w0[j * DIN + k2 * 2];
        s_w0p[idx] = pack2(v.x, v.y);
    }
    for (int idx = tid; idx < H0 * 16; idx += 256) {
        int k = idx / 16, q = idx - k * 16;
        s_w1p[idx] = pack2(w1[(2 * q) * H0 + k], w1[(2 * q + 1) * H0 + k]);
    }
    if (tid < H1) {
        s_w2p01[tid] = pack2(w2[0 * H1 + tid], w2[1 * H1 + tid]);
        s_w2p23[tid] = pack2(w2[2 * H1 + tid], w2[3 * H1 + tid]);
    }
    __syncthreads();

    int node = blockIdx.x * 256 + tid;
    if (node >= n) return;

    // seg = last g with ptr[g] <= node
    int lo = 0, hi = B;
    while (lo < hi) {
        int mid = (lo + hi + 1) >> 1;
        if (s_ptr[mid] <= node) lo = mid; else hi = mid - 1;
    }
    int seg = lo;

    // node features: 11 float4 loads -> 22 packed pairs
    u64 a2[22];
    const float4* ar = (const float4*)(node_attr + (size_t)node * FEAT);
    #pragma unroll
    for (int i = 0; i < 11; i++) {
        float4 v = __ldg(&ar[i]);
        a2[2 * i]     = pack2(v.x, v.y);
        a2[2 * i + 1] = pack2(v.z, v.w);
    }

    const float* e0r = g_e0 + (size_t)seg * H0;

    // layer-1 accumulators, packed pairs, init from b1
    u64 acc1p[16];
    const float2* b1p = (const float2*)b1;
    #pragma unroll
    for (int q = 0; q < 16; q++) {
        float2 v = __ldg(&b1p[q]);
        acc1p[q] = pack2(v.x, v.y);
    }

    #pragma unroll 2
    for (int j = 0; j < H0; j++) {
        // acc starts as {e0[j], 0}: lo lane carries bias+embed, hi lane pure dot
        u64 acc2 = pack2(__ldg(&e0r[j]), 0.0f);
        const u64* wr = &s_w0p[j * 22];
        #pragma unroll
        for (int k2 = 0; k2 < 22; k2++)
            acc2 = ffma2(wr[k2], a2[k2], acc2);
        float alo, ahi;
        unpack2(acc2, alo, ahi);
        float h = swishf(alo + ahi);

        u64 hh = pack2(h, h);
        const u64* w1r = &s_w1p[j * 16];
        #pragma unroll
        for (int q = 0; q < 16; q++)
            acc1p[q] = ffma2(w1r[q], hh, acc1p[q]);
    }

    u64 o01 = pack2(__ldg(&b2[0]), __ldg(&b2[1]));
    u64 o23 = pack2(__ldg(&b2[2]), __ldg(&b2[3]));
    #pragma unroll 4
    for (int q = 0; q < 16; q++) {
        float x0, x1;
        unpack2(acc1p[q], x0, x1);
        float h0 = swishf(x0);
        float h1 = swishf(x1);
        u64 h00 = pack2(h0, h0);
        u64 h11 = pack2(h1, h1);
        o01 = ffma2(s_w2p01[2 * q],     h00, o01);
        o23 = ffma2(s_w2p23[2 * q],     h00, o23);
        o01 = ffma2(s_w2p01[2 * q + 1], h11, o01);
        o23 = ffma2(s_w2p23[2 * q + 1], h11, o23);
    }

    float o0, o1, o2, o3;
    unpack2(o01, o0, o1);
    unpack2(o23, o2, o3);
    float is = __ldg(&g_invstd[seg]);
    float4 o;
    o.x = swishf(o0) * is;
    o.y = swishf(o1) * is;
    o.z = swishf(o2) * is;
    o.w = swishf(o3) * is;
    *(float4*)(out + (size_t)node * 4) = o;
}

// ---------------------------------------------------------------------------
extern "C" void kernel_launch(void* const* d_in, const int* in_sizes, int n_in,
                              void* d_out, int out_size)
{
    const float* node_attr = (const float*)d_in[0];
    const float* t   = (const float*)d_in[1];
    const int*   ptr = (const int*)d_in[2];
    const float* W_f = (const float*)d_in[3];
    const float* ew  = (const float*)d_in[4];
    const float* eb  = (const float*)d_in[5];
    const float* w0  = (const float*)d_in[6];
    const float* b0  = (const float*)d_in[7];
    const float* w1  = (const float*)d_in[8];
    const float* b1  = (const float*)d_in[9];
    const float* w2  = (const float*)d_in[10];
    const float* b2  = (const float*)d_in[11];
    float* out = (float*)d_out;

    int B = in_sizes[1];           // 4096
    int n = in_sizes[0] / FEAT;    // 1048576

    k_embed<<<256, 128>>>(t, W_f, ew, eb, B);
    k_e0   <<<256, 128>>>(w0, b0, B);
    k_main <<<(n + 255) / 256, 256>>>(node_attr, ptr, w0, w1, b1, w2, b2, out, n, B);
}

// round 11
// speedup vs baseline: 1.2804x; 1.2804x over previous
#include <cuda_runtime.h>
#include <math.h>

#define FEAT 44
#define TED 84
#define HALF_TED 42
#define DIN 128
#define H0 64
#define H1 32
#define MAXB 4096
#define GW 4                            /* warps per block in k_graph */
#define LN_SIGMA 3.2188758248682006f    /* ln(25) */
#define TWO_PI 6.28318530717958647692f

typedef unsigned long long u64;

// Scratch (no dynamic allocation allowed)
__device__ float g_e0[MAXB * H0];
__device__ float g_invstd[MAXB];

__device__ __forceinline__ float swishf(float x) {
    return __fdividef(x, 1.0f + __expf(-x));
}

// ---- packed f32x2 helpers (Blackwell FFMA2) ----
__device__ __forceinline__ u64 ffma2(u64 a, u64 b, u64 c) {
    u64 d;
    asm("fma.rn.f32x2 %0, %1, %2, %3;" : "=l"(d) : "l"(a), "l"(b), "l"(c));
    return d;
}
__device__ __forceinline__ u64 pack2(float lo, float hi) {
    u64 r;
    asm("mov.b64 %0, {%1, %2};" : "=l"(r) : "f"(lo), "f"(hi));
    return r;
}
__device__ __forceinline__ void unpack2(u64 v, float& lo, float& hi) {
    asm("mov.b64 {%0, %1}, %2;" : "=f"(lo), "=f"(hi) : "l"(v));
}

// ---------------------------------------------------------------------------
// k_graph: fused per-graph pipeline, ONE WARP PER GRAPH (no block syncs in
// the loop — removes the serialization that made k_embed 31us).
//   temb = [sin,cos](2pi * t * W_f)          (42 lanes x 2 rounds)
//   emb  = swish(temb @ ewT + eb)            (84 outs, 3 lane-rounds)
//   e0   = b0 + emb @ w0[:,44:128].T         (64 outs, 2 lane-rounds)
//   invstd                                    (lane 0)
// ---------------------------------------------------------------------------
__global__ __launch_bounds__(128) void k_graph(
    const float* __restrict__ t, const float* __restrict__ W_f,
    const float* __restrict__ ew, const float* __restrict__ eb,
    const float* __restrict__ w0, const float* __restrict__ b0, int B)
{
    __shared__ float s_ewT[TED * TED];   // [i*TED+o] = ew[o*TED+i]
    __shared__ float s_w0t[TED * H0];    // [i*H0+o]  = w0[o*DIN+FEAT+i]
    __shared__ float s_wf[HALF_TED];
    __shared__ float s_eb[TED];
    __shared__ float s_b0[H0];
    __shared__ float s_temb[GW][TED];
    __shared__ float s_emb[GW][TED];

    int tid = threadIdx.x;
    int wid = tid >> 5, lane = tid & 31;

    for (int idx = tid; idx < TED * TED; idx += blockDim.x) {
        int o = idx / TED, i = idx - o * TED;
        s_ewT[i * TED + o] = ew[idx];
    }
    for (int idx = tid; idx < TED * H0; idx += blockDim.x) {
        int o = idx / TED, i = idx - o * TED;
        s_w0t[i * H0 + o] = w0[o * DIN + FEAT + i];
    }
    if (tid < HALF_TED) s_wf[tid] = W_f[tid];
    if (tid < TED)      s_eb[tid] = eb[tid];
    if (tid < H0)       s_b0[tid] = b0[tid];
    __syncthreads();

    int gw = blockIdx.x * GW + wid;
    int nwarps = gridDim.x * GW;

    for (int g = gw; g < B; g += nwarps) {
        float tg = __ldg(&t[g]);

        #pragma unroll
        for (int r = 0; r < 2; r++) {
            int idx = lane + 32 * r;
            if (idx < HALF_TED) {
                float s, c;
                sincosf(tg * s_wf[idx] * TWO_PI, &s, &c);
                s_temb[wid][idx] = s;
                s_temb[wid][idx + HALF_TED] = c;
            }
        }
        __syncwarp();

        #pragma unroll
        for (int r = 0; r < 3; r++) {
            int o = lane + 32 * r;
            if (o < TED) {
                float acc = s_eb[o];
                #pragma unroll 4
                for (int i = 0; i < TED; i++)
                    acc = fmaf(s_temb[wid][i], s_ewT[i * TED + o], acc);
                s_emb[wid][o] = swishf(acc);
            }
        }
        __syncwarp();

        #pragma unroll
        for (int r = 0; r < 2; r++) {
            int o = lane + 32 * r;
            float acc = s_b0[o];
            #pragma unroll 4
            for (int i = 0; i < TED; i++)
                acc = fmaf(s_emb[wid][i], s_w0t[i * H0 + o], acc);
            g_e0[(size_t)g * H0 + o] = acc;
        }
        if (lane == 0) {
            float v = (expf(2.0f * tg * LN_SIGMA) - 1.0f) * (0.5f / LN_SIGMA);
            g_invstd[g] = rsqrtf(v);
        }
        __syncwarp();
    }
}

// ---------------------------------------------------------------------------
// k_main: per-node MLP, packed f32x2 math, LDS.128 weight staging.
// Per j-iteration: 11 LDS.128 (w0) + 8 LDS.128 (w1) = 19 shared loads
// feeding 22+16 = 38 FFMA2 (was 38 LDS.64 -> LDS-issue-bound at 506us).
// ---------------------------------------------------------------------------
__global__ __launch_bounds__(256) void k_main(
    const float* __restrict__ node_attr, const int* __restrict__ ptr,
    const float* __restrict__ w0, const float* __restrict__ w1,
    const float* __restrict__ b1, const float* __restrict__ w2,
    const float* __restrict__ b2, float* __restrict__ out,
    int n, int B)
{
    __shared__ int s_ptr[MAXB + 1];
    __shared__ ulonglong2 s_w0v[H0 * 11]; // [j][k4] = {pack(w0[j][4k4],w0[j][4k4+1]), pack(..+2,..+3)}
    __shared__ ulonglong2 s_w1v[H0 * 8];  // [k][qq] = {pack(w1[4qq][k],w1[4qq+1][k]), pack(w1[4qq+2][k],w1[4qq+3][k])}
    __shared__ u64 s_w2p01[H1];           // {w2[0][k], w2[1][k]}
    __shared__ u64 s_w2p23[H1];           // {w2[2][k], w2[3][k]}

    int tid = threadIdx.x;
    for (int idx = tid; idx <= B; idx += 256) s_ptr[idx] = ptr[idx];
    for (int idx = tid; idx < H0 * 11; idx += 256) {
        int j = idx / 11, k4 = idx - j * 11;
        float4 v = *(const float4*)&w0[j * DIN + k4 * 4];
        ulonglong2 p;
        p.x = pack2(v.x, v.y);
        p.y = pack2(v.z, v.w);
        s_w0v[idx] = p;
    }
    for (int idx = tid; idx < H0 * 8; idx += 256) {
        int k = idx / 8, qq = idx - k * 8;
        ulonglong2 p;
        p.x = pack2(w1[(4 * qq + 0) * H0 + k], w1[(4 * qq + 1) * H0 + k]);
        p.y = pack2(w1[(4 * qq + 2) * H0 + k], w1[(4 * qq + 3) * H0 + k]);
        s_w1v[idx] = p;
    }
    if (tid < H1) {
        s_w2p01[tid] = pack2(w2[0 * H1 + tid], w2[1 * H1 + tid]);
        s_w2p23[tid] = pack2(w2[2 * H1 + tid], w2[3 * H1 + tid]);
    }
    __syncthreads();

    int node = blockIdx.x * 256 + tid;
    if (node >= n) return;

    // seg = last g with ptr[g] <= node
    int lo = 0, hi = B;
    while (lo < hi) {
        int mid = (lo + hi + 1) >> 1;
        if (s_ptr[mid] <= node) lo = mid; else hi = mid - 1;
    }
    int seg = lo;

    // node features: 11 float4 loads -> 22 packed pairs
    u64 a2[22];
    const float4* ar = (const float4*)(node_attr + (size_t)node * FEAT);
    #pragma unroll
    for (int i = 0; i < 11; i++) {
        float4 v = __ldg(&ar[i]);
        a2[2 * i]     = pack2(v.x, v.y);
        a2[2 * i + 1] = pack2(v.z, v.w);
    }

    const float* e0r = g_e0 + (size_t)seg * H0;

    u64 acc1p[16];
    const float2* b1p = (const float2*)b1;
    #pragma unroll
    for (int q = 0; q < 16; q++) {
        float2 v = __ldg(&b1p[q]);
        acc1p[q] = pack2(v.x, v.y);
    }

    #pragma unroll 2
    for (int j = 0; j < H0; j++) {
        // lo lane carries bias+embed (precomputed e0), hi lane pure dot
        u64 acc2 = pack2(__ldg(&e0r[j]), 0.0f);
        const ulonglong2* wr = &s_w0v[j * 11];
        #pragma unroll
        for (int k4 = 0; k4 < 11; k4++) {
            ulonglong2 w = wr[k4];
            acc2 = ffma2(w.x, a2[2 * k4],     acc2);
            acc2 = ffma2(w.y, a2[2 * k4 + 1], acc2);
        }
        float alo, ahi;
        unpack2(acc2, alo, ahi);
        float h = swishf(alo + ahi);

        u64 hh = pack2(h, h);
        const ulonglong2* w1r = &s_w1v[j * 8];
        #pragma unroll
        for (int qq = 0; qq < 8; qq++) {
            ulonglong2 w = w1r[qq];
            acc1p[2 * qq]     = ffma2(w.x, hh, acc1p[2 * qq]);
            acc1p[2 * qq + 1] = ffma2(w.y, hh, acc1p[2 * qq + 1]);
        }
    }

    u64 o01 = pack2(__ldg(&b2[0]), __ldg(&b2[1]));
    u64 o23 = pack2(__ldg(&b2[2]), __ldg(&b2[3]));
    #pragma unroll 4
    for (int q = 0; q < 16; q++) {
        float x0, x1;
        unpack2(acc1p[q], x0, x1);
        float h0 = swishf(x0);
        float h1 = swishf(x1);
        u64 h00 = pack2(h0, h0);
        u64 h11 = pack2(h1, h1);
        o01 = ffma2(s_w2p01[2 * q],     h00, o01);
        o23 = ffma2(s_w2p23[2 * q],     h00, o23);
        o01 = ffma2(s_w2p01[2 * q + 1], h11, o01);
        o23 = ffma2(s_w2p23[2 * q + 1], h11, o23);
    }

    float o0, o1, o2, o3;
    unpack2(o01, o0, o1);
    unpack2(o23, o2, o3);
    float is = __ldg(&g_invstd[seg]);
    float4 o;
    o.x = swishf(o0) * is;
    o.y = swishf(o1) * is;
    o.z = swishf(o2) * is;
    o.w = swishf(o3) * is;
    *(float4*)(out + (size_t)node * 4) = o;
}

// ---------------------------------------------------------------------------
extern "C" void kernel_launch(void* const* d_in, const int* in_sizes, int n_in,
                              void* d_out, int out_size)
{
    const float* node_attr = (const float*)d_in[0];
    const float* t   = (const float*)d_in[1];
    const int*   ptr = (const int*)d_in[2];
    const float* W_f = (const float*)d_in[3];
    const float* ew  = (const float*)d_in[4];
    const float* eb  = (const float*)d_in[5];
    const float* w0  = (const float*)d_in[6];
    const float* b0  = (const float*)d_in[7];
    const float* w1  = (const float*)d_in[8];
    const float* b1  = (const float*)d_in[9];
    const float* w2  = (const float*)d_in[10];
    const float* b2  = (const float*)d_in[11];
    float* out = (float*)d_out;

    int B = in_sizes[1];           // 4096
    int n = in_sizes[0] / FEAT;    // 1048576

    k_graph<<<128, 128>>>(t, W_f, ew, eb, w0, b0, B);
    k_main <<<(n + 255) / 256, 256>>>(node_attr, ptr, w0, w1, b1, w2, b2, out, n, B);
}

// round 13
// speedup vs baseline: 1.4037x; 1.0963x over previous
#include <cuda_runtime.h>
#include <math.h>

#define FEAT 44
#define TED 84
#define HALF_TED 42
#define DIN 128
#define H0 64
#define H1 32
#define MAXB 4096
#define GW 4
#define LN_SIGMA 3.2188758248682006f    /* ln(25) */
#define TWO_PI 6.28318530717958647692f

typedef unsigned long long u64;

__device__ float g_e0[MAXB * H0];
__device__ float g_invstd[MAXB];

__device__ __forceinline__ float swishf(float x) {
    return __fdividef(x, 1.0f + __expf(-x));
}

__device__ __forceinline__ u64 ffma2(u64 a, u64 b, u64 c) {
    u64 d;
    asm("fma.rn.f32x2 %0, %1, %2, %3;" : "=l"(d) : "l"(a), "l"(b), "l"(c));
    return d;
}
__device__ __forceinline__ u64 pack2(float lo, float hi) {
    u64 r;
    asm("mov.b64 %0, {%1, %2};" : "=l"(r) : "f"(lo), "f"(hi));
    return r;
}
__device__ __forceinline__ void unpack2(u64 v, float& lo, float& hi) {
    asm("mov.b64 {%0, %1}, %2;" : "=f"(lo), "=f"(hi) : "l"(v));
}

// ---------------------------------------------------------------------------
// k_graph: one warp per graph (4096 warps total -> no serial graph chains).
// ---------------------------------------------------------------------------
__global__ __launch_bounds__(128) void k_graph(
    const float* __restrict__ t, const float* __restrict__ W_f,
    const float* __restrict__ ew, const float* __restrict__ eb,
    const float* __restrict__ w0, const float* __restrict__ b0, int B)
{
    __shared__ float s_ewT[TED * TED];
    __shared__ float s_w0t[TED * H0];
    __shared__ float s_wf[HALF_TED];
    __shared__ float s_eb[TED];
    __shared__ float s_b0[H0];
    __shared__ float s_temb[GW][TED];
    __shared__ float s_emb[GW][TED];

    int tid = threadIdx.x;
    int wid = tid >> 5, lane = tid & 31;

    for (int idx = tid; idx < TED * TED; idx += blockDim.x) {
        int o = idx / TED, i = idx - o * TED;
        s_ewT[i * TED + o] = ew[idx];
    }
    for (int idx = tid; idx < TED * H0; idx += blockDim.x) {
        int o = idx / TED, i = idx - o * TED;
        s_w0t[i * H0 + o] = w0[o * DIN + FEAT + i];
    }
    if (tid < HALF_TED) s_wf[tid] = W_f[tid];
    if (tid < TED)      s_eb[tid] = eb[tid];
    if (tid < H0)       s_b0[tid] = b0[tid];
    __syncthreads();

    int g = blockIdx.x * GW + wid;
    if (g >= B) return;

    float tg = __ldg(&t[g]);

    #pragma unroll
    for (int r = 0; r < 2; r++) {
        int idx = lane + 32 * r;
        if (idx < HALF_TED) {
            float s, c;
            sincosf(tg * s_wf[idx] * TWO_PI, &s, &c);
            s_temb[wid][idx] = s;
            s_temb[wid][idx + HALF_TED] = c;
        }
    }
    __syncwarp();

    #pragma unroll
    for (int r = 0; r < 3; r++) {
        int o = lane + 32 * r;
        if (o < TED) {
            float acc = s_eb[o];
            #pragma unroll 4
            for (int i = 0; i < TED; i++)
                acc = fmaf(s_temb[wid][i], s_ewT[i * TED + o], acc);
            s_emb[wid][o] = swishf(acc);
        }
    }
    __syncwarp();

    #pragma unroll
    for (int r = 0; r < 2; r++) {
        int o = lane + 32 * r;
        float acc = s_b0[o];
        #pragma unroll 4
        for (int i = 0; i < TED; i++)
            acc = fmaf(s_emb[wid][i], s_w0t[i * H0 + o], acc);
        g_e0[(size_t)g * H0 + o] = acc;
    }
    if (lane == 0) {
        float v = (expf(2.0f * tg * LN_SIGMA) - 1.0f) * (0.5f / LN_SIGMA);
        g_invstd[g] = rsqrtf(v);
    }
}

// ---------------------------------------------------------------------------
// k_main: TWO adjacent nodes per thread — every weight LDS serves 2 nodes.
// Per j-iter: 19 LDS.128 (weights, shared) + 76 FFMA2 (2 nodes) -> the
// 0.5 LDS/cyc : 2 FMA/cyc pipe ratio is exactly balanced (was L1=91%, fma=42%).
// ---------------------------------------------------------------------------
__global__ __launch_bounds__(128) void k_main(
    const float* __restrict__ node_attr, const int* __restrict__ ptr,
    const float* __restrict__ w0, const float* __restrict__ w1,
    const float* __restrict__ b1, const float* __restrict__ w2,
    const float* __restrict__ b2, float* __restrict__ out,
    int n, int B)
{
    __shared__ int s_ptr[MAXB + 1];
    __shared__ ulonglong2 s_w0v[H0 * 11];
    __shared__ ulonglong2 s_w1v[H0 * 8];
    __shared__ u64 s_w2p01[H1];
    __shared__ u64 s_w2p23[H1];

    int tid = threadIdx.x;
    for (int idx = tid; idx <= B; idx += 128) s_ptr[idx] = ptr[idx];
    for (int idx = tid; idx < H0 * 11; idx += 128) {
        int j = idx / 11, k4 = idx - j * 11;
        float4 v = *(const float4*)&w0[j * DIN + k4 * 4];
        ulonglong2 p;
        p.x = pack2(v.x, v.y);
        p.y = pack2(v.z, v.w);
        s_w0v[idx] = p;
    }
    for (int idx = tid; idx < H0 * 8; idx += 128) {
        int k = idx / 8, qq = idx - k * 8;
        ulonglong2 p;
        p.x = pack2(w1[(4 * qq + 0) * H0 + k], w1[(4 * qq + 1) * H0 + k]);
        p.y = pack2(w1[(4 * qq + 2) * H0 + k], w1[(4 * qq + 3) * H0 + k]);
        s_w1v[idx] = p;
    }
    if (tid < H1) {
        s_w2p01[tid] = pack2(w2[0 * H1 + tid], w2[1 * H1 + tid]);
        s_w2p23[tid] = pack2(w2[2 * H1 + tid], w2[3 * H1 + tid]);
    }
    __syncthreads();

    int node0 = (blockIdx.x * 128 + tid) * 2;
    if (node0 >= n) return;
    int node1 = node0 + 1;
    bool has1 = node1 < n;

    // seg for node0 (binary search), then seg1 incrementally
    int lo = 0, hi = B;
    while (lo < hi) {
        int mid = (lo + hi + 1) >> 1;
        if (s_ptr[mid] <= node0) lo = mid; else hi = mid - 1;
    }
    int seg0 = lo;
    int seg1 = seg0;
    while (seg1 < B - 1 && s_ptr[seg1 + 1] <= node1) seg1++;

    // features for both nodes
    u64 a2a[22], a2b[22];
    {
        const float4* ar0 = (const float4*)(node_attr + (size_t)node0 * FEAT);
        #pragma unroll
        for (int i = 0; i < 11; i++) {
            float4 v = __ldg(&ar0[i]);
            a2a[2 * i]     = pack2(v.x, v.y);
            a2a[2 * i + 1] = pack2(v.z, v.w);
        }
        const float4* ar1 = (const float4*)(node_attr + (size_t)node1 * FEAT);
        #pragma unroll
        for (int i = 0; i < 11; i++) {
            float4 v = has1 ? __ldg(&ar1[i]) : make_float4(0.f, 0.f, 0.f, 0.f);
            a2b[2 * i]     = pack2(v.x, v.y);
            a2b[2 * i + 1] = pack2(v.z, v.w);
        }
    }

    const float* e0a = g_e0 + (size_t)seg0 * H0;
    const float* e0b = g_e0 + (size_t)seg1 * H0;

    u64 acc1pa[16], acc1pb[16];
    const float2* b1p = (const float2*)b1;
    #pragma unroll
    for (int q = 0; q < 16; q++) {
        float2 v = __ldg(&b1p[q]);
        u64 pv = pack2(v.x, v.y);
        acc1pa[q] = pv;
        acc1pb[q] = pv;
    }

    #pragma unroll 2
    for (int j = 0; j < H0; j++) {
        u64 acc2a = pack2(__ldg(&e0a[j]), 0.0f);
        u64 acc2b = pack2(__ldg(&e0b[j]), 0.0f);
        const ulonglong2* wr = &s_w0v[j * 11];
        #pragma unroll
        for (int k4 = 0; k4 < 11; k4++) {
            ulonglong2 w = wr[k4];
            acc2a = ffma2(w.x, a2a[2 * k4],     acc2a);
            acc2a = ffma2(w.y, a2a[2 * k4 + 1], acc2a);
            acc2b = ffma2(w.x, a2b[2 * k4],     acc2b);
            acc2b = ffma2(w.y, a2b[2 * k4 + 1], acc2b);
        }
        float alo, ahi, blo, bhi;
        unpack2(acc2a, alo, ahi);
        unpack2(acc2b, blo, bhi);
        float ha = swishf(alo + ahi);
        float hb = swishf(blo + bhi);

        u64 hha = pack2(ha, ha);
        u64 hhb = pack2(hb, hb);
        const ulonglong2* w1r = &s_w1v[j * 8];
        #pragma unroll
        for (int qq = 0; qq < 8; qq++) {
            ulonglong2 w = w1r[qq];
            acc1pa[2 * qq]     = ffma2(w.x, hha, acc1pa[2 * qq]);
            acc1pa[2 * qq + 1] = ffma2(w.y, hha, acc1pa[2 * qq + 1]);
            acc1pb[2 * qq]     = ffma2(w.x, hhb, acc1pb[2 * qq]);
            acc1pb[2 * qq + 1] = ffma2(w.y, hhb, acc1pb[2 * qq + 1]);
        }
    }

    float bb0 = __ldg(&b2[0]), bb1 = __ldg(&b2[1]);
    float bb2 = __ldg(&b2[2]), bb3 = __ldg(&b2[3]);
    u64 oa01 = pack2(bb0, bb1), oa23 = pack2(bb2, bb3);
    u64 ob01 = oa01, ob23 = oa23;
    #pragma unroll 4
    for (int q = 0; q < 16; q++) {
        u64 w01a = s_w2p01[2 * q],     w23a = s_w2p23[2 * q];
        u64 w01b = s_w2p01[2 * q + 1], w23b = s_w2p23[2 * q + 1];
        float x0, x1;
        unpack2(acc1pa[q], x0, x1);
        float h0 = swishf(x0), h1 = swishf(x1);
        u64 h00 = pack2(h0, h0), h11 = pack2(h1, h1);
        oa01 = ffma2(w01a, h00, oa01);
        oa23 = ffma2(w23a, h00, oa23);
        oa01 = ffma2(w01b, h11, oa01);
        oa23 = ffma2(w23b, h11, oa23);
        unpack2(acc1pb[q], x0, x1);
        h0 = swishf(x0); h1 = swishf(x1);
        h00 = pack2(h0, h0); h11 = pack2(h1, h1);
        ob01 = ffma2(w01a, h00, ob01);
        ob23 = ffma2(w23a, h00, ob23);
        ob01 = ffma2(w01b, h11, ob01);
        ob23 = ffma2(w23b, h11, ob23);
    }

    float o0, o1, o2, o3;
    float is0 = __ldg(&g_invstd[seg0]);
    unpack2(oa01, o0, o1);
    unpack2(oa23, o2, o3);
    float4 oA;
    oA.x = swishf(o0) * is0;
    oA.y = swishf(o1) * is0;
    oA.z = swishf(o2) * is0;
    oA.w = swishf(o3) * is0;
    *(float4*)(out + (size_t)node0 * 4) = oA;

    if (has1) {
        float is1 = __ldg(&g_invstd[seg1]);
        unpack2(ob01, o0, o1);
        unpack2(ob23, o2, o3);
        float4 oB;
        oB.x = swishf(o0) * is1;
        oB.y = swishf(o1) * is1;
        oB.z = swishf(o2) * is1;
        oB.w = swishf(o3) * is1;
        *(float4*)(out + (size_t)node1 * 4) = oB;
    }
}

// ---------------------------------------------------------------------------
extern "C" void kernel_launch(void* const* d_in, const int* in_sizes, int n_in,
                              void* d_out, int out_size)
{
    const float* node_attr = (const float*)d_in[0];
    const float* t   = (const float*)d_in[1];
    const int*   ptr = (const int*)d_in[2];
    const float* W_f = (const float*)d_in[3];
    const float* ew  = (const float*)d_in[4];
    const float* eb  = (const float*)d_in[5];
    const float* w0  = (const float*)d_in[6];
    const float* b0  = (const float*)d_in[7];
    const float* w1  = (const float*)d_in[8];
    const float* b1  = (const float*)d_in[9];
    const float* w2  = (const float*)d_in[10];
    const float* b2  = (const float*)d_in[11];
    float* out = (float*)d_out;

    int B = in_sizes[1];           // 4096
    int n = in_sizes[0] / FEAT;    // 1048576

    int gblocks = (B + GW - 1) / GW;               // 1024: one warp per graph
    k_graph<<<gblocks, 128>>>(t, W_f, ew, eb, w0, b0, B);
    int pairs = (n + 1) / 2;
    k_main<<<(pairs + 127) / 128, 128>>>(node_attr, ptr, w0, w1, b1, w2, b2, out, n, B);
}